// round 2
// baseline (speedup 1.0000x reference)
#include <cuda_runtime.h>
#include <cstddef>

#define NW    100000
#define VD    128
#define BATCH 16384
#define KNUM  26
#define NSLOT 7   // ceil(26/4) k-slots per warp

// 51.2 MB transposed copy of O: OT[word][v]. Static device scratch (no alloc).
__device__ float g_OT[(size_t)NW * VD];

// ---------------------------------------------------------------------------
// Kernel 1: transpose O [VD, NW] -> OT [NW, VD], tiled 32x32 via smem.
// Grid: (NW/32, VD/32) = (3125, 4). Block: (32, 8). DRAM-bound (~6 TB/s).
// ---------------------------------------------------------------------------
__global__ void transpose_kernel(const float* __restrict__ O) {
    __shared__ float tile[32][33];  // +1 pad: conflict-free transpose read
    const int w0 = blockIdx.x * 32;
    const int v0 = blockIdx.y * 32;
    const int tx = threadIdx.x;
    const int ty = threadIdx.y;

#pragma unroll
    for (int j = 0; j < 32; j += 8) {
        tile[ty + j][tx] = O[(size_t)(v0 + ty + j) * NW + (w0 + tx)];
    }
    __syncthreads();
#pragma unroll
    for (int j = 0; j < 32; j += 8) {
        g_OT[(size_t)(w0 + ty + j) * VD + (v0 + tx)] = tile[tx][ty + j];
    }
}

// ---------------------------------------------------------------------------
// Kernel 2: one block (128 threads = 4 warps) per batch element b.
// Each warp owns k = wid, wid+4, ... (7 predicated slots, fully unrolled):
//   phase 1: batch-load 7 word ids (uniform-address broadcast LDGs)
//   phase 2: batch-load 7 OT rows as LDG.128 x 32 lanes  -> MLP = 7
//   phase 3: FMA + butterfly shuffle reduce, lane 0 stores.
// No smem, no __syncthreads.
// ---------------------------------------------------------------------------
__global__ void score_kernel(const int* __restrict__ doc_ids,
                             const int* __restrict__ tnids,
                             const float* __restrict__ D,
                             float* __restrict__ out) {
    const int b    = blockIdx.x;
    const int t    = threadIdx.x;
    const int lane = t & 31;
    const int wid  = t >> 5;

    const int doc = __ldg(&doc_ids[b]);
    const float4 dv =
        __ldg(reinterpret_cast<const float4*>(D + (size_t)doc * VD) + lane);

    // phase 1: word ids (independent, batched)
    int words[NSLOT];
#pragma unroll
    for (int i = 0; i < NSLOT; i++) {
        const int k = wid + 4 * i;
        words[i] = (k < KNUM) ? __ldg(&tnids[b * KNUM + k]) : 0;
    }

    // phase 2: OT rows (front-batched LDG.128, MLP = 7)
    float4 w4[NSLOT];
#pragma unroll
    for (int i = 0; i < NSLOT; i++) {
        const int k = wid + 4 * i;
        if (k < KNUM) {
            w4[i] = *(reinterpret_cast<const float4*>(
                          g_OT + (size_t)words[i] * VD) + lane);
        }
    }

    // phase 3: dot + reduce + store
#pragma unroll
    for (int i = 0; i < NSLOT; i++) {
        const int k = wid + 4 * i;
        if (k < KNUM) {
            float s = dv.x * w4[i].x + dv.y * w4[i].y +
                      dv.z * w4[i].z + dv.w * w4[i].w;
            s += __shfl_xor_sync(0xffffffffu, s, 16);
            s += __shfl_xor_sync(0xffffffffu, s, 8);
            s += __shfl_xor_sync(0xffffffffu, s, 4);
            s += __shfl_xor_sync(0xffffffffu, s, 2);
            s += __shfl_xor_sync(0xffffffffu, s, 1);
            if (lane == 0) out[b * KNUM + k] = s;
        }
    }
}

// ---------------------------------------------------------------------------
// Inputs (metadata order): context_ids[B] i32 (unused), doc_ids[B] i32,
// target_noise_ids[B*K] i32, D[NUM_DOCS*VD] f32, O[VD*NW] f32.
// Output: out[B*K] f32.
// ---------------------------------------------------------------------------
extern "C" void kernel_launch(void* const* d_in, const int* in_sizes, int n_in,
                              void* d_out, int out_size) {
    const int*   doc_ids = (const int*)d_in[1];
    const int*   tnids   = (const int*)d_in[2];
    const float* D       = (const float*)d_in[3];
    const float* O       = (const float*)d_in[4];
    float*       out     = (float*)d_out;

    dim3 tg(NW / 32, VD / 32);
    dim3 tb(32, 8);
    transpose_kernel<<<tg, tb>>>(O);

    score_kernel<<<BATCH, VD>>>(doc_ids, tnids, D, out);
}